// round 1
// baseline (speedup 1.0000x reference)
#include <cuda_runtime.h>
#include <math.h>

#define B_ 8
#define N_ 2048
#define FIN 128
#define FOUT 64
#define ALPHA_ 0.2f
#define NNODE (B_*N_)

#define BM 128     // rows (i) per block
#define BJ 64      // j tile
#define PTS 132    // P-tile smem stride (pad: 128+4, keeps float4 alignment, kills bank conflicts)

// Scratch (allocation-free rule: __device__ globals)
__device__ float g_Wh[(size_t)NNODE*FOUT];
__device__ float g_f1[NNODE];
__device__ float g_f2[NNODE];
__device__ float g_E1p[NNODE];   // exp(f1)
__device__ float g_E1n[NNODE];   // exp(alpha*f1)
__device__ float g_E2p[NNODE];   // exp(f2)
__device__ float g_E2n[NNODE];   // exp(alpha*f2)

// ---------------------------------------------------------------------------
// Prep: Wh = h @ W, f1 = Wh.a1, f2 = Wh.a2, plus the 4 per-node exponentials.
// One warp per node row. 2048 blocks x 256 threads.
// ---------------------------------------------------------------------------
__global__ void __launch_bounds__(256) prep_kernel(const float* __restrict__ h,
                                                   const float* __restrict__ W,
                                                   const float* __restrict__ a) {
    __shared__ float Ws[FIN*FOUT];        // 32KB
    const int tid = threadIdx.x;
    {
        const float4* W4 = (const float4*)W;
        float4* Ws4 = (float4*)Ws;
#pragma unroll
        for (int x = 0; x < (FIN*FOUT/4)/256; x++)
            Ws4[tid + x*256] = W4[tid + x*256];
    }
    __syncthreads();

    const int warp = tid >> 5, lane = tid & 31;
    const int row = blockIdx.x * 8 + warp;

    // h row in registers, broadcast via shfl
    const float4 hv = ((const float4*)(h + (size_t)row*FIN))[lane];
    float hreg[4] = {hv.x, hv.y, hv.z, hv.w};

    float acc0 = 0.f, acc1 = 0.f;
#pragma unroll
    for (int k = 0; k < FIN; k++) {
        float hk = __shfl_sync(0xffffffffu, hreg[k & 3], k >> 2);
        acc0 = fmaf(hk, Ws[k*FOUT + lane],      acc0);
        acc1 = fmaf(hk, Ws[k*FOUT + lane + 32], acc1);
    }
    g_Wh[(size_t)row*FOUT + lane]      = acc0;
    g_Wh[(size_t)row*FOUT + lane + 32] = acc1;

    float p1 = acc0*a[lane]      + acc1*a[lane+32];
    float p2 = acc0*a[FOUT+lane] + acc1*a[FOUT+lane+32];
#pragma unroll
    for (int o = 16; o > 0; o >>= 1) {
        p1 += __shfl_xor_sync(0xffffffffu, p1, o);
        p2 += __shfl_xor_sync(0xffffffffu, p2, o);
    }
    if (lane == 0) {
        g_f1[row]  = p1;
        g_f2[row]  = p2;
        g_E1p[row] = expf(p1);
        g_E1n[row] = expf(ALPHA_*p1);
        g_E2p[row] = expf(p2);
        g_E2n[row] = expf(ALPHA_*p2);
    }
}

// ---------------------------------------------------------------------------
// Main: for each (b, 128-row tile): stream j in tiles of 64.
//   P[i][j] = adj ? (s>=0 ? E1p_i*E2p_j : E1n_i*E2n_j) : 0   (no exp in the loop)
//   acc[i][:] += P[i][j] * Wh[j][:]   (register-tiled GEMM from smem)
//   Z[i]     += sum_j P[i][j]
// Final: out = acc / Z. No online softmax needed (scores bounded).
// ---------------------------------------------------------------------------
__global__ void __launch_bounds__(256) gat_main(const int* __restrict__ adj,
                                                float* __restrict__ out) {
    extern __shared__ float sm[];
    float* Pt   = sm;                 // [BJ][PTS]  transposed P tile: Pt[j][i]
    float* Whs  = Pt + BJ*PTS;        // [BJ][FOUT]
    float* f1r  = Whs + BJ*FOUT;      // [BM]
    float* E1pr = f1r + BM;           // [BM]
    float* E1nr = E1pr + BM;          // [BM]
    float* Zs   = E1nr + BM;          // [BM]

    const int tid = threadIdx.x;
    const int b  = blockIdx.y;
    const int i0 = blockIdx.x * BM;
    const int nodeBase = b * N_;

    if (tid < BM) {
        const int node = nodeBase + i0 + tid;
        f1r[tid]  = g_f1[node];
        E1pr[tid] = g_E1p[node];
        E1nr[tid] = g_E1n[node];
        Zs[tid]   = 0.f;
    }

    const int tc = tid & 15;    // col group: cols [tc*4, tc*4+4)
    const int tr = tid >> 4;    // row group: rows [tr*8, tr*8+8)
    const int jl = tid & 63;    // j lane for P computation
    const int gg = tid >> 6;    // row-group for P computation (0..3)

    float acc[8][4];
#pragma unroll
    for (int r = 0; r < 8; r++)
#pragma unroll
        for (int c = 0; c < 4; c++) acc[r][c] = 0.f;

    const int* adjBase = adj + (size_t)b*N_*N_ + (size_t)i0*N_ + jl;

    for (int jt = 0; jt < N_/BJ; jt++) {
        const int j0 = jt * BJ;
        __syncthreads();   // previous GEMM done reading Pt/Whs

        // Load Wh tile [BJ x FOUT] (coalesced float4)
        {
            const float4* src = (const float4*)(g_Wh + (size_t)(nodeBase + j0)*FOUT);
            float4* dst = (float4*)Whs;
#pragma unroll
            for (int x = 0; x < (BJ*FOUT/4)/256; x++)
                dst[tid + x*256] = src[tid + x*256];
        }

        // Per-thread column constants (global reads, L2-resident, 64 distinct/block)
        const int cnode = nodeBase + j0 + jl;
        const float f2j = g_f2[cnode];
        const float e2p = g_E2p[cnode];
        const float e2n = g_E2n[cnode];

        // Compute P tile: thread covers column jl, 8 groups of 4 consecutive rows
        const int* ap = adjBase + j0;
#pragma unroll
        for (int q = 0; q < 8; q++) {
            const int ib = gg*4 + q*16;
            float pv[4];
#pragma unroll
            for (int m = 0; m < 4; m++) {
                const int i = ib + m;
                const int av = ap[(size_t)i * N_];
                const float s = f1r[i] + f2j;
                const float pe = (s >= 0.f) ? (E1pr[i]*e2p) : (E1nr[i]*e2n);
                pv[m] = (av != 0) ? pe : 0.f;
            }
            *(float4*)&Pt[jl*PTS + ib] = make_float4(pv[0], pv[1], pv[2], pv[3]);
        }
        __syncthreads();

        // Z pass (cheap: 128 threads, conflict-free thanks to PTS=132)
        if (tid < BM) {
            float z = 0.f;
#pragma unroll
            for (int j = 0; j < BJ; j++) z += Pt[j*PTS + tid];
            Zs[tid] += z;
        }

        // Register-tiled GEMM: acc[8][4] += Pt[j][tr*8..] * Whs[j][tc*4..]
#pragma unroll 8
        for (int j = 0; j < BJ; j++) {
            const float4 p0 = *(const float4*)&Pt[j*PTS + tr*8];
            const float4 p1 = *(const float4*)&Pt[j*PTS + tr*8 + 4];
            const float4 wv = *(const float4*)&Whs[j*FOUT + tc*4];
            const float pr[8] = {p0.x,p0.y,p0.z,p0.w,p1.x,p1.y,p1.z,p1.w};
            const float wc[4] = {wv.x,wv.y,wv.z,wv.w};
#pragma unroll
            for (int r = 0; r < 8; r++)
#pragma unroll
                for (int c = 0; c < 4; c++)
                    acc[r][c] = fmaf(pr[r], wc[c], acc[r][c]);
        }
    }

    __syncthreads();
#pragma unroll
    for (int r = 0; r < 8; r++) {
        const int i = tr*8 + r;
        const float inv = 1.0f / Zs[i];
        float4 o = make_float4(acc[r][0]*inv, acc[r][1]*inv,
                               acc[r][2]*inv, acc[r][3]*inv);
        *(float4*)&out[((size_t)(nodeBase + i0 + i))*FOUT + tc*4] = o;
    }
}

// ---------------------------------------------------------------------------
extern "C" void kernel_launch(void* const* d_in, const int* in_sizes, int n_in,
                              void* d_out, int out_size) {
    const float* h   = (const float*)d_in[0];
    const float* W   = (const float*)d_in[1];
    const float* a   = (const float*)d_in[2];
    const int*   adj = (const int*)d_in[3];
    float* out = (float*)d_out;

    prep_kernel<<<NNODE/8, 256>>>(h, W, a);

    const int smem = (BJ*PTS + BJ*FOUT + 3*BM + BM) * (int)sizeof(float);  // 52224 B
    cudaFuncSetAttribute(gat_main, cudaFuncAttributeMaxDynamicSharedMemorySize, smem);
    dim3 grid(N_/BM, B_);
    gat_main<<<grid, 256, smem>>>(adj, out);
}

// round 3
// speedup vs baseline: 2.2340x; 2.2340x over previous
#include <cuda_runtime.h>
#include <math.h>
#include <stdint.h>

#define B_ 8
#define N_ 2048
#define FIN 128
#define FOUT 64
#define ALPHA_ 0.2f
#define NNODE (B_*N_)

#define SPLIT 4
#define JCH (N_/SPLIT)      // 512 j per CTA
#define BK 32               // j per stage
#define NST (JCH/BK)        // 16 stages
#define BM 128              // rows per CTA

// smem strides chosen for conflict-free fragment LDS / STS.128:
//  P[i][k]  stride 36: (36i+k)%32 = (4i+k)%32 bijective over gid(8)xtig(4)
//  B[k][n]  stride 72: (72k+n)%32 = (8k+n)%32 bijective over tig(4)xgid(8)
#define PSTR 36
#define BSTR 72
#define PBUF (BM*PSTR)              // 4608 floats
#define BBUF (BK*BSTR)              // 2304 floats
#define OFF_P0 0
#define OFF_P1 PBUF
#define OFF_B0 (2*PBUF)
#define OFF_B1 (2*PBUF + BBUF)
#define SMEM_BYTES ((2*PBUF + 2*BBUF)*4)   // 55296

// ---------------- scratch (__device__ globals: allocation-free rule) -------
__device__ float g_Wh[(size_t)NNODE*FOUT];          // tf32-rounded Wh
__device__ float g_f1[NNODE], g_f2[NNODE];
__device__ float g_E1p[NNODE], g_E1n[NNODE];
__device__ float g_E2p[NNODE], g_E2n[NNODE];
__device__ float g_acc[(size_t)SPLIT*NNODE*FOUT];   // 16 MB partials
__device__ float g_Z[(size_t)SPLIT*NNODE];

__device__ __forceinline__ float cvt_tf32(float x) {
    uint32_t u;
    asm("cvt.rna.tf32.f32 %0, %1;" : "=r"(u) : "f"(x));
    return __uint_as_float(u);
}

// ---------------------------------------------------------------------------
// Prep: Wh = h@W (tf32-rounded store), f1/f2 and the 4 per-node exponentials.
// One warp per node row.
// ---------------------------------------------------------------------------
__global__ void __launch_bounds__(256) prep_kernel(const float* __restrict__ h,
                                                   const float* __restrict__ W,
                                                   const float* __restrict__ a) {
    __shared__ float Ws[FIN*FOUT];
    const int tid = threadIdx.x;
    {
        const float4* W4 = (const float4*)W;
        float4* Ws4 = (float4*)Ws;
#pragma unroll
        for (int x = 0; x < (FIN*FOUT/4)/256; x++)
            Ws4[tid + x*256] = W4[tid + x*256];
    }
    __syncthreads();

    const int warp = tid >> 5, lane = tid & 31;
    const int row = blockIdx.x * 8 + warp;

    const float4 hv = ((const float4*)(h + (size_t)row*FIN))[lane];
    float hreg[4] = {hv.x, hv.y, hv.z, hv.w};

    float acc0 = 0.f, acc1 = 0.f;
#pragma unroll
    for (int k = 0; k < FIN; k++) {
        float hk = __shfl_sync(0xffffffffu, hreg[k & 3], k >> 2);
        acc0 = fmaf(hk, Ws[k*FOUT + lane],      acc0);
        acc1 = fmaf(hk, Ws[k*FOUT + lane + 32], acc1);
    }
    g_Wh[(size_t)row*FOUT + lane]      = cvt_tf32(acc0);
    g_Wh[(size_t)row*FOUT + lane + 32] = cvt_tf32(acc1);

    float p1 = acc0*a[lane]      + acc1*a[lane+32];
    float p2 = acc0*a[FOUT+lane] + acc1*a[FOUT+lane+32];
#pragma unroll
    for (int o = 16; o > 0; o >>= 1) {
        p1 += __shfl_xor_sync(0xffffffffu, p1, o);
        p2 += __shfl_xor_sync(0xffffffffu, p2, o);
    }
    if (lane == 0) {
        g_f1[row]  = p1;
        g_f2[row]  = p2;
        g_E1p[row] = expf(p1);
        g_E1n[row] = expf(ALPHA_*p1);
        g_E2p[row] = expf(p2);
        g_E2n[row] = expf(ALPHA_*p2);
    }
}

// ---------------------------------------------------------------------------
// Main: CTA = (i-tile 128 rows, batch b, j-chunk 512). Stages of BK=32.
// CUDA cores build tf32 P tile in smem; warps run m16n8k8 tf32 mma.sync.
// Z accumulated from the SAME tf32 P values (quantization cancels in softmax).
// Partial (acc, Z) written to global; combine kernel normalizes.
// ---------------------------------------------------------------------------
__global__ void __launch_bounds__(256,2) gat_mma(const int* __restrict__ adj) {
    extern __shared__ float smf[];
    const int tid = threadIdx.x;
    const int b  = blockIdx.y;
    const int sp = blockIdx.z;
    const int i0 = blockIdx.x * BM;
    const int js = sp * JCH;
    const int nodeBase = b * N_;

    const int rg = tid >> 3;          // P rows rg*4..+3
    const int cg = tid & 7;           // P cols cg*4..+3 (within BK)
    const int wid = tid >> 5, lane = tid & 31;
    const int gid = lane >> 2, tig = lane & 3;
    const int wm = wid * 16;          // warp's M offset

    // per-thread i-scalars
    float f1i[4], e1pi[4], e1ni[4];
#pragma unroll
    for (int r = 0; r < 4; r++) {
        const int nd = nodeBase + i0 + rg*4 + r;
        f1i[r]  = g_f1[nd];
        e1pi[r] = g_E1p[nd];
        e1ni[r] = g_E1n[nd];
    }
    float zacc[4] = {0.f, 0.f, 0.f, 0.f};

    float acc[8][4];
#pragma unroll
    for (int nt = 0; nt < 8; nt++)
#pragma unroll
        for (int c = 0; c < 4; c++) acc[nt][c] = 0.f;

    const size_t adjBase = (size_t)b*N_*N_ + (size_t)(i0 + rg*4)*N_ + js + cg*4;
    const int e0k = tid >> 4, e0n = (tid & 15) * 4;

    int4 a4[4]; float4 f2v, p2v, n2v, bw0, bw1;

#define PREFETCH(S) do {                                                          \
        const size_t _jo = (size_t)(S)*BK;                                        \
        _Pragma("unroll")                                                         \
        for (int r = 0; r < 4; r++)                                               \
            a4[r] = __ldcs((const int4*)(adj + adjBase + (size_t)r*N_ + _jo));    \
        const int _cn = nodeBase + js + (S)*BK + cg*4;                            \
        f2v = *(const float4*)(g_f2  + _cn);                                      \
        p2v = *(const float4*)(g_E2p + _cn);                                      \
        n2v = *(const float4*)(g_E2n + _cn);                                      \
        const size_t _wb = (size_t)(nodeBase + js + (S)*BK) * FOUT;               \
        bw0 = *(const float4*)(g_Wh + _wb + (size_t)e0k*FOUT + e0n);              \
        bw1 = *(const float4*)(g_Wh + _wb + (size_t)(e0k+16)*FOUT + e0n);         \
    } while (0)

    PREFETCH(0);

    for (int s = 0; s < NST; s++) {
        // ---- compute P values (tf32-rounded; also feeds Z) ----
        const float f2a[4] = {f2v.x, f2v.y, f2v.z, f2v.w};
        const float pa[4]  = {p2v.x, p2v.y, p2v.z, p2v.w};
        const float na[4]  = {n2v.x, n2v.y, n2v.z, n2v.w};
        float pv[4][4];
#pragma unroll
        for (int r = 0; r < 4; r++) {
            const int am[4] = {a4[r].x, a4[r].y, a4[r].z, a4[r].w};
#pragma unroll
            for (int c = 0; c < 4; c++) {
                const float sv = f1i[r] + f2a[c];
                float v = (sv >= 0.f) ? (e1pi[r]*pa[c]) : (e1ni[r]*na[c]);
                v = (am[c] != 0) ? v : 0.f;
                v = cvt_tf32(v);
                zacc[r] += v;
                pv[r][c] = v;
            }
        }

        float* P  = smf + ((s & 1) ? OFF_P1 : OFF_P0);
        float* Bm = smf + ((s & 1) ? OFF_B1 : OFF_B0);

        // ---- STS P tile [128 x 32] (stride 36; STS.128 conflict-free) ----
#pragma unroll
        for (int r = 0; r < 4; r++)
            *(float4*)&P[(rg*4 + r)*PSTR + cg*4] =
                make_float4(pv[r][0], pv[r][1], pv[r][2], pv[r][3]);

        // ---- STS B tile [32 x 64] (stride 72) ----
        *(float4*)&Bm[e0k*BSTR + e0n]       = bw0;
        *(float4*)&Bm[(e0k+16)*BSTR + e0n]  = bw1;

        __syncthreads();

        if (s + 1 < NST) PREFETCH(s + 1);   // LDG latency hides under GEMM

        // ---- GEMM: 4 k-steps x 8 n-tiles of m16n8k8 tf32 mma.sync ----
        const float* Ap = P  + (wm + gid)*PSTR + tig;
        const float* Bp = Bm + tig*BSTR + gid;
#pragma unroll
        for (int kq = 0; kq < 4; kq++) {
            const uint32_t A0 = __float_as_uint(Ap[kq*8]);
            const uint32_t A1 = __float_as_uint(Ap[kq*8 + 8*PSTR]);
            const uint32_t A2 = __float_as_uint(Ap[kq*8 + 4]);
            const uint32_t A3 = __float_as_uint(Ap[kq*8 + 4 + 8*PSTR]);
            const float* Bk = Bp + kq*8*BSTR;
#pragma unroll
            for (int nt = 0; nt < 8; nt++) {
                const uint32_t B0 = __float_as_uint(Bk[nt*8]);
                const uint32_t B1 = __float_as_uint(Bk[nt*8 + 4*BSTR]);
                asm("mma.sync.aligned.m16n8k8.row.col.f32.tf32.tf32.f32 "
                    "{%0,%1,%2,%3}, {%4,%5,%6,%7}, {%8,%9}, {%0,%1,%2,%3};"
                    : "+f"(acc[nt][0]), "+f"(acc[nt][1]),
                      "+f"(acc[nt][2]), "+f"(acc[nt][3])
                    : "r"(A0), "r"(A1), "r"(A2), "r"(A3), "r"(B0), "r"(B1));
            }
        }
    }

    // ---- Z partial: reduce over cg (lanes xor 1,2,4) and store ----
#pragma unroll
    for (int r = 0; r < 4; r++) {
        zacc[r] += __shfl_xor_sync(0xffffffffu, zacc[r], 1);
        zacc[r] += __shfl_xor_sync(0xffffffffu, zacc[r], 2);
        zacc[r] += __shfl_xor_sync(0xffffffffu, zacc[r], 4);
    }
    if (cg == 0) {
#pragma unroll
        for (int r = 0; r < 4; r++)
            g_Z[(size_t)sp*NNODE + nodeBase + i0 + rg*4 + r] = zacc[r];
    }

    // ---- acc partial store (D fragment: rows gid/gid+8, cols nt*8+tig*2) ----
    const size_t obase = ((size_t)sp*NNODE + nodeBase + i0) * FOUT;
#pragma unroll
    for (int nt = 0; nt < 8; nt++) {
        const int col = nt*8 + tig*2;
        *(float2*)&g_acc[obase + (size_t)(wm + gid)*FOUT + col] =
            make_float2(acc[nt][0], acc[nt][1]);
        *(float2*)&g_acc[obase + (size_t)(wm + gid + 8)*FOUT + col] =
            make_float2(acc[nt][2], acc[nt][3]);
    }
}

// ---------------------------------------------------------------------------
// Combine: out[node][f] = sum_sp acc / sum_sp Z
// ---------------------------------------------------------------------------
__global__ void __launch_bounds__(256) combine_kernel(float* __restrict__ out) {
    const int idx = blockIdx.x * 256 + threadIdx.x;   // 0 .. NNODE*16-1
    const int node = idx >> 4;
    const int f4 = (idx & 15) * 4;
    float sx = 0.f, sy = 0.f, sz = 0.f, sw = 0.f, z = 0.f;
#pragma unroll
    for (int sp = 0; sp < SPLIT; sp++) {
        const float4 v = *(const float4*)&g_acc[((size_t)sp*NNODE + node)*FOUT + f4];
        sx += v.x; sy += v.y; sz += v.z; sw += v.w;
        z += g_Z[(size_t)sp*NNODE + node];
    }
    const float inv = 1.0f / z;
    *(float4*)&out[(size_t)node*FOUT + f4] = make_float4(sx*inv, sy*inv, sz*inv, sw*inv);
}

// ---------------------------------------------------------------------------
extern "C" void kernel_launch(void* const* d_in, const int* in_sizes, int n_in,
                              void* d_out, int out_size) {
    const float* h   = (const float*)d_in[0];
    const float* W   = (const float*)d_in[1];
    const float* a   = (const float*)d_in[2];
    const int*   adj = (const int*)d_in[3];
    float* out = (float*)d_out;

    prep_kernel<<<NNODE/8, 256>>>(h, W, a);

    cudaFuncSetAttribute(gat_mma, cudaFuncAttributeMaxDynamicSharedMemorySize, SMEM_BYTES);
    dim3 grid(N_/BM, B_, SPLIT);
    gat_mma<<<grid, 256, SMEM_BYTES>>>(adj);

    combine_kernel<<<(NNODE*16)/256, 256>>>(out);
}

// round 4
// speedup vs baseline: 3.0460x; 1.3635x over previous
#include <cuda_runtime.h>
#include <math.h>
#include <stdint.h>

#define B_ 8
#define N_ 2048
#define FIN 128
#define FOUT 64
#define NNODE (B_*N_)

#define SPLIT 2
#define JCH (N_/SPLIT)     // 1024
#define BK 64
#define NST (JCH/BK)       // 16
#define BM 128

// gat smem (float units)
#define PSTR 68
#define BSTR 72
#define PBUF (BM*PSTR)                 // 8704
#define BBUF (BK*BSTR)                 // 4608
#define OFF_P0 0
#define OFF_P1 PBUF
#define OFF_B0 (2*PBUF)
#define OFF_B1 (2*PBUF + BBUF)
#define GAT_SMEM ((2*PBUF + 2*BBUF)*4) // 106496 B

// prep smem (float units)
#define HSTR 132
#define PREP_SMEM ((FIN*HSTR + 2*FIN*BSTR + FIN)*4)   // 141824 B

// ---------------- scratch ----------------------------------------------------
__device__ float g_Wh[(size_t)NNODE*FOUT];            // tf32-rounded
__device__ float g_E1p[NNODE], g_E1n[NNODE];
__device__ float g_E2p[NNODE], g_E2n[NNODE];
__device__ float g_acc[(size_t)SPLIT*NNODE*FOUT];     // 8 MB partials
__device__ float g_Z[(size_t)SPLIT*NNODE];

// ---------------- helpers ----------------------------------------------------
__device__ __forceinline__ uint32_t smem_u32(const void* p) {
    uint32_t a;
    asm("{ .reg .u64 t; cvta.to.shared.u64 t, %1; cvt.u32.u64 %0, t; }" : "=r"(a) : "l"(p));
    return a;
}
__device__ __forceinline__ float cvt_tf32(float x) {
    uint32_t u;
    asm("cvt.rna.tf32.f32 %0, %1;" : "=r"(u) : "f"(x));
    return __uint_as_float(u);
}
__device__ __forceinline__ void cp16(uint32_t dst, const void* src) {
    asm volatile("cp.async.cg.shared.global [%0], [%1], 16;" :: "r"(dst), "l"(src));
}
#define CP_COMMIT() asm volatile("cp.async.commit_group;" ::: "memory")
#define CP_WAIT0()  asm volatile("cp.async.wait_group 0;" ::: "memory")

#define MMA_TF32(D, A0, A1, A2, A3, Bb0, Bb1)                                   \
    asm("mma.sync.aligned.m16n8k8.row.col.f32.tf32.tf32.f32 "                   \
        "{%0,%1,%2,%3}, {%4,%5,%6,%7}, {%8,%9}, {%0,%1,%2,%3};"                 \
        : "+f"((D)[0]), "+f"((D)[1]), "+f"((D)[2]), "+f"((D)[3])                \
        : "r"(A0), "r"(A1), "r"(A2), "r"(A3), "r"(Bb0), "r"(Bb1))

// ---------------------------------------------------------------------------
// Prep: Wh = h@W via tf32 mma with hi/lo split (fp32-accurate), tf32-rounded
// store; f1/f2 dot-products from accumulators; 4 per-node exponentials.
// Grid 128 CTAs x 256 threads; CTA = 128 rows.
// ---------------------------------------------------------------------------
__global__ void __launch_bounds__(256) prep_mma(const float* __restrict__ h,
                                                const float* __restrict__ W,
                                                const float* __restrict__ a) {
    extern __shared__ float sp_[];
    float* hs  = sp_;                       // [128][132]
    float* WsH = hs + FIN*HSTR;             // [128][72]
    float* WsL = WsH + FIN*BSTR;            // [128][72]
    float* as_ = WsL + FIN*BSTR;            // [128]

    const int tid = threadIdx.x;
    const int i0 = blockIdx.x * 128;

    if (tid < 128) as_[tid] = a[tid];

    // Stage W with hi/lo tf32 split
#pragma unroll
    for (int it = 0; it < 8; it++) {
        const int lin = it*256 + tid;           // float4 units over 128x64
        const int k = lin >> 4, c4 = (lin & 15) * 4;
        const float4 w = *(const float4*)(W + k*FOUT + c4);
        const float hx = cvt_tf32(w.x), hy = cvt_tf32(w.y);
        const float hz = cvt_tf32(w.z), hw = cvt_tf32(w.w);
        *(float4*)(WsH + k*BSTR + c4) = make_float4(hx, hy, hz, hw);
        *(float4*)(WsL + k*BSTR + c4) = make_float4(cvt_tf32(w.x-hx), cvt_tf32(w.y-hy),
                                                    cvt_tf32(w.z-hz), cvt_tf32(w.w-hw));
    }
    // Stage h tile [128][128]
#pragma unroll
    for (int it = 0; it < 16; it++) {
        const int lin = it*256 + tid;
        const int r = lin >> 5, c = (lin & 31) * 4;
        *(float4*)(hs + r*HSTR + c) = *(const float4*)(h + (size_t)(i0 + r)*FIN + c);
    }
    __syncthreads();

    const int wid = tid >> 5, lane = tid & 31;
    const int gid = lane >> 2, tig = lane & 3;
    const int wm = wid * 16;

    float acc[8][4] = {};
    const float* Ap = hs + (wm + gid)*HSTR + tig;
    const float* BH = WsH + tig*BSTR + gid;
    const float* BL = WsL + tig*BSTR + gid;

#pragma unroll
    for (int kq = 0; kq < 16; kq++) {
        const float x0 = Ap[kq*8],     x1 = Ap[kq*8 + 8*HSTR];
        const float x2 = Ap[kq*8 + 4], x3 = Ap[kq*8 + 4 + 8*HSTR];
        const float h0 = cvt_tf32(x0), h1 = cvt_tf32(x1);
        const float h2 = cvt_tf32(x2), h3 = cvt_tf32(x3);
        const uint32_t AH0 = __float_as_uint(h0), AH1 = __float_as_uint(h1);
        const uint32_t AH2 = __float_as_uint(h2), AH3 = __float_as_uint(h3);
        const uint32_t AL0 = __float_as_uint(cvt_tf32(x0-h0));
        const uint32_t AL1 = __float_as_uint(cvt_tf32(x1-h1));
        const uint32_t AL2 = __float_as_uint(cvt_tf32(x2-h2));
        const uint32_t AL3 = __float_as_uint(cvt_tf32(x3-h3));
        const float* bh = BH + kq*8*BSTR;
        const float* bl = BL + kq*8*BSTR;
#pragma unroll
        for (int nt = 0; nt < 8; nt++) {
            const uint32_t bh0 = __float_as_uint(bh[nt*8]);
            const uint32_t bh1 = __float_as_uint(bh[nt*8 + 4*BSTR]);
            const uint32_t bl0 = __float_as_uint(bl[nt*8]);
            const uint32_t bl1 = __float_as_uint(bl[nt*8 + 4*BSTR]);
            MMA_TF32(acc[nt], AH0, AH1, AH2, AH3, bh0, bh1);
            MMA_TF32(acc[nt], AH0, AH1, AH2, AH3, bl0, bl1);
            MMA_TF32(acc[nt], AL0, AL1, AL2, AL3, bh0, bh1);
        }
    }

    // Epilogue: store tf32-rounded Wh, compute f1/f2, store exponentials
    const int r0 = i0 + wm + gid, r1 = r0 + 8;
    float f1a = 0.f, f2a = 0.f, f1b = 0.f, f2b = 0.f;
#pragma unroll
    for (int nt = 0; nt < 8; nt++) {
        const int c = nt*8 + tig*2;
        const float a10 = as_[c], a11 = as_[c+1];
        const float a20 = as_[64+c], a21 = as_[64+c+1];
        f1a += acc[nt][0]*a10 + acc[nt][1]*a11;
        f2a += acc[nt][0]*a20 + acc[nt][1]*a21;
        f1b += acc[nt][2]*a10 + acc[nt][3]*a11;
        f2b += acc[nt][2]*a20 + acc[nt][3]*a21;
        *(float2*)(g_Wh + (size_t)r0*FOUT + c) =
            make_float2(cvt_tf32(acc[nt][0]), cvt_tf32(acc[nt][1]));
        *(float2*)(g_Wh + (size_t)r1*FOUT + c) =
            make_float2(cvt_tf32(acc[nt][2]), cvt_tf32(acc[nt][3]));
    }
#pragma unroll
    for (int o = 1; o <= 2; o <<= 1) {
        f1a += __shfl_xor_sync(0xffffffffu, f1a, o);
        f2a += __shfl_xor_sync(0xffffffffu, f2a, o);
        f1b += __shfl_xor_sync(0xffffffffu, f1b, o);
        f2b += __shfl_xor_sync(0xffffffffu, f2b, o);
    }
    if (tig == 0) {
        g_E1p[r0] = expf(f1a);      g_E1n[r0] = expf(0.2f*f1a);
        g_E2p[r0] = expf(f2a);      g_E2n[r0] = expf(0.2f*f2a);
        g_E1p[r1] = expf(f1b);      g_E1n[r1] = expf(0.2f*f1b);
        g_E2p[r1] = expf(f2b);      g_E2n[r1] = expf(0.2f*f2b);
    }
}

// ---------------------------------------------------------------------------
// Main: CTA = (128 rows, batch, 1024-j chunk); 16 stages of BK=64.
// P = max(e1p*e2p, e1n*e2n) masked by adj, tf32-rounded (exact in mma).
// B tile = Wh[64x64] + ones column (col 64) -> Z computed by tensor core.
// Warp grid 4m x 2n. cp.async stages B; single sync per stage.
// ---------------------------------------------------------------------------
__global__ void __launch_bounds__(256,2) gat_mma(const int* __restrict__ adj) {
    extern __shared__ float smf[];
    const uint32_t sb = smem_u32(smf);
    const int tid = threadIdx.x;
    const int b  = blockIdx.y;
    const int sp = blockIdx.z;
    const int i0 = blockIdx.x * BM;
    const int js = sp * JCH;
    const int nodeBase = b * N_;

    const int rg = tid >> 4;          // rows rg*8..+7 (P build)
    const int cg = tid & 15;          // cols cg*4..+3 within BK
    const int wid = tid >> 5, lane = tid & 31;
    const int gid = lane >> 2, tig = lane & 3;
    const int am = (wid & 3) * 32;    // warp m-offset (2 m16 tiles)
    const int nw = wid >> 2;          // warp n-half

    // per-thread row scalars
    float e1p[8], e1n[8];
#pragma unroll
    for (int r = 0; r < 8; r++) {
        const int node = nodeBase + i0 + rg*8 + r;
        e1p[r] = g_E1p[node];
        e1n[r] = g_E1n[node];
    }

    // ones/zeros columns 64..71 of both B buffers (written once)
#pragma unroll
    for (int it = 0; it < 4; it++) {
        const int lin = it*256 + tid;                    // 0..1023
        const int buf = lin >> 9;
        const int k = (lin >> 3) & 63, c = 64 + (lin & 7);
        smf[(buf ? OFF_B1 : OFF_B0) + k*BSTR + c] = (c == 64) ? 1.f : 0.f;
    }

    const int ek = tid >> 4, en = (tid & 15) * 4;        // B staging mapping

#define CPB(S) do {                                                             \
        const float* _src = g_Wh + ((size_t)(nodeBase + js + (S)*BK + ek))*FOUT + en; \
        const uint32_t _dst = sb + ((((S)&1) ? OFF_B1 : OFF_B0) + ek*BSTR + en)*4;    \
        _Pragma("unroll")                                                       \
        for (int q = 0; q < 4; q++)                                             \
            cp16(_dst + (uint32_t)(q*16*BSTR*4), _src + (size_t)q*16*FOUT);     \
        CP_COMMIT();                                                            \
    } while (0)

    const int* adjB = adj + (size_t)b*N_*N_ + (size_t)(i0 + rg*8)*N_ + js + cg*4;
    int4 a4[8]; float4 p2v, n2v;

#define PF(S) do {                                                              \
        _Pragma("unroll")                                                       \
        for (int r = 0; r < 8; r++)                                             \
            a4[r] = __ldcs((const int4*)(adjB + (size_t)r*N_ + (S)*BK));        \
        const int _cn = nodeBase + js + (S)*BK + cg*4;                          \
        p2v = *(const float4*)(g_E2p + _cn);                                    \
        n2v = *(const float4*)(g_E2n + _cn);                                    \
    } while (0)

    CPB(0);
    PF(0);

    float acc[2][5][4] = {};

    for (int s = 0; s < NST; s++) {
        float* Pw = smf + ((s & 1) ? OFF_P1 : OFF_P0);
        const float p2a[4] = {p2v.x, p2v.y, p2v.z, p2v.w};
        const float n2a[4] = {n2v.x, n2v.y, n2v.z, n2v.w};

        // P build + STS (8 rows x 4 cols per thread)
#pragma unroll
        for (int r = 0; r < 8; r++) {
            const int am4[4] = {a4[r].x, a4[r].y, a4[r].z, a4[r].w};
            float pv[4];
#pragma unroll
            for (int c = 0; c < 4; c++) {
                const float v = fmaxf(e1p[r]*p2a[c], e1n[r]*n2a[c]);
                pv[c] = cvt_tf32(am4[c] != 0 ? v : 0.f);
            }
            *(float4*)&Pw[(rg*8 + r)*PSTR + cg*4] =
                make_float4(pv[0], pv[1], pv[2], pv[3]);
        }

        if (s + 1 < NST) PF(s + 1);        // early LDG issue

        CP_WAIT0();                        // B(s) landed
        __syncthreads();                   // P(s)+B(s) visible; prev GEMM done
        if (s + 1 < NST) CPB(s + 1);

        // GEMM(s): 2 m-tiles x (4 or 5) n-tiles x 8 k-steps
        const float* P  = smf + ((s & 1) ? OFF_P1 : OFF_P0);
        const float* Bs = smf + ((s & 1) ? OFF_B1 : OFF_B0);
        const float* Ap0 = P + (am + gid)*PSTR + tig;
        const float* Ap1 = P + (am + 16 + gid)*PSTR + tig;
        const float* Bp = Bs + tig*BSTR + gid + nw*32;
#pragma unroll
        for (int kq = 0; kq < 8; kq++) {
            const uint32_t A00 = __float_as_uint(Ap0[kq*8]);
            const uint32_t A01 = __float_as_uint(Ap0[kq*8 + 8*PSTR]);
            const uint32_t A02 = __float_as_uint(Ap0[kq*8 + 4]);
            const uint32_t A03 = __float_as_uint(Ap0[kq*8 + 4 + 8*PSTR]);
            const uint32_t A10 = __float_as_uint(Ap1[kq*8]);
            const uint32_t A11 = __float_as_uint(Ap1[kq*8 + 8*PSTR]);
            const uint32_t A12 = __float_as_uint(Ap1[kq*8 + 4]);
            const uint32_t A13 = __float_as_uint(Ap1[kq*8 + 4 + 8*PSTR]);
            const float* Bk = Bp + kq*8*BSTR;
#pragma unroll
            for (int nt = 0; nt < 4; nt++) {
                const uint32_t b0 = __float_as_uint(Bk[nt*8]);
                const uint32_t b1 = __float_as_uint(Bk[nt*8 + 4*BSTR]);
                MMA_TF32(acc[0][nt], A00, A01, A02, A03, b0, b1);
                MMA_TF32(acc[1][nt], A10, A11, A12, A13, b0, b1);
            }
            if (nw == 1) {                  // ones tile (ntv=8, cols 64..71)
                const uint32_t b0 = __float_as_uint(Bk[32]);
                const uint32_t b1 = __float_as_uint(Bk[32 + 4*BSTR]);
                MMA_TF32(acc[0][4], A00, A01, A02, A03, b0, b1);
                MMA_TF32(acc[1][4], A10, A11, A12, A13, b0, b1);
            }
        }
    }

    // store partials
    const size_t obase = ((size_t)sp*NNODE + nodeBase + i0) * FOUT;
#pragma unroll
    for (int mt = 0; mt < 2; mt++) {
        const int row = am + mt*16 + gid;
#pragma unroll
        for (int nt = 0; nt < 4; nt++) {
            const int col = (nw*4 + nt)*8 + tig*2;
            *(float2*)&g_acc[obase + (size_t)row*FOUT + col] =
                make_float2(acc[mt][nt][0], acc[mt][nt][1]);
            *(float2*)&g_acc[obase + (size_t)(row + 8)*FOUT + col] =
                make_float2(acc[mt][nt][2], acc[mt][nt][3]);
        }
        if (nw == 1 && tig == 0) {
            g_Z[(size_t)sp*NNODE + nodeBase + i0 + row]     = acc[mt][4][0];
            g_Z[(size_t)sp*NNODE + nodeBase + i0 + row + 8] = acc[mt][4][2];
        }
    }
}

// ---------------------------------------------------------------------------
__global__ void __launch_bounds__(256) combine_kernel(float* __restrict__ out) {
    const int idx = blockIdx.x * 256 + threadIdx.x;
    const int node = idx >> 4;
    const int f4 = (idx & 15) * 4;
    float sx = 0.f, sy = 0.f, sz = 0.f, sw = 0.f, z = 0.f;
#pragma unroll
    for (int sp = 0; sp < SPLIT; sp++) {
        const float4 v = *(const float4*)&g_acc[((size_t)sp*NNODE + node)*FOUT + f4];
        sx += v.x; sy += v.y; sz += v.z; sw += v.w;
        z += g_Z[(size_t)sp*NNODE + node];
    }
    const float inv = 1.0f / z;
    *(float4*)&out[(size_t)node*FOUT + f4] = make_float4(sx*inv, sy*inv, sz*inv, sw*inv);
}

// ---------------------------------------------------------------------------
extern "C" void kernel_launch(void* const* d_in, const int* in_sizes, int n_in,
                              void* d_out, int out_size) {
    const float* h   = (const float*)d_in[0];
    const float* W   = (const float*)d_in[1];
    const float* a   = (const float*)d_in[2];
    const int*   adj = (const int*)d_in[3];
    float* out = (float*)d_out;

    cudaFuncSetAttribute(prep_mma, cudaFuncAttributeMaxDynamicSharedMemorySize, PREP_SMEM);
    prep_mma<<<NNODE/128, 256, PREP_SMEM>>>(h, W, a);

    cudaFuncSetAttribute(gat_mma, cudaFuncAttributeMaxDynamicSharedMemorySize, GAT_SMEM);
    dim3 grid(N_/BM, B_, SPLIT);
    gat_mma<<<grid, 256, GAT_SMEM>>>(adj);

    combine_kernel<<<(NNODE*16)/256, 256>>>(out);
}

// round 5
// speedup vs baseline: 3.2120x; 1.0545x over previous
#include <cuda_runtime.h>
#include <cuda_bf16.h>
#include <math.h>
#include <stdint.h>

#define B_ 8
#define N_ 2048
#define FIN 128
#define FOUT 64
#define NNODE (B_*N_)

#define SPLIT 2
#define JCH (N_/SPLIT)      // 1024
#define BK 64
#define NST (JCH/BK)        // 16
#define BM 128

// ---- gat smem (bf16 units), strides give conflict-free ldmatrix/LDS/STS ----
#define PSTRB 72                     // 144 B row stride
#define PBUFB (BM*PSTRB)             // 9216
#define BROWS 136                    // 64 hi + 64 lo + 8 (ones/zeros)
#define BBUFB (BROWS*PSTRB)          // 9792
#define OFF_P0 0
#define OFF_P1 PBUFB
#define OFF_B0 (2*PBUFB)
#define OFF_B1 (2*PBUFB + BBUFB)
#define GAT_SMEM ((2*PBUFB + 2*BBUFB)*2)   // 76032 B

// ---- prep smem (float units) ----
#define HSTR 132
#define WSTR 72
#define PREP_SMEM ((64*HSTR + 2*FIN*WSTR + 128 + 256)*4)   // 109056 B

// ---------------- scratch ----------------------------------------------------
__device__ __nv_bfloat16 g_WhTh[(size_t)B_*FOUT*N_];   // [b][col][k] hi
__device__ __nv_bfloat16 g_WhTl[(size_t)B_*FOUT*N_];   // [b][col][k] lo
__device__ float g_E1p[NNODE], g_E1n[NNODE];
__device__ float g_E2p[NNODE], g_E2n[NNODE];
__device__ float g_acc[(size_t)SPLIT*NNODE*FOUT];
__device__ float g_Z[(size_t)SPLIT*NNODE];

// ---------------- helpers ----------------------------------------------------
__device__ __forceinline__ uint32_t smem_u32(const void* p) {
    uint32_t a;
    asm("{ .reg .u64 t; cvta.to.shared.u64 t, %1; cvt.u32.u64 %0, t; }" : "=r"(a) : "l"(p));
    return a;
}
__device__ __forceinline__ float cvt_tf32(float x) {
    uint32_t u;
    asm("cvt.rna.tf32.f32 %0, %1;" : "=r"(u) : "f"(x));
    return __uint_as_float(u);
}
__device__ __forceinline__ void cp16(uint32_t dst, const void* src) {
    asm volatile("cp.async.cg.shared.global [%0], [%1], 16;" :: "r"(dst), "l"(src));
}
#define CP_COMMIT() asm volatile("cp.async.commit_group;" ::: "memory")
#define CP_WAIT0()  asm volatile("cp.async.wait_group 0;" ::: "memory")

// pack (lo=v0, hi=v1) into bf16x2
__device__ __forceinline__ uint32_t pack_bf16x2(float v0, float v1) {
    uint32_t r;
    asm("cvt.rn.bf16x2.f32 %0, %1, %2;" : "=r"(r) : "f"(v1), "f"(v0));
    return r;
}

#define MMA_TF32(D, A0, A1, A2, A3, Bb0, Bb1)                                   \
    asm("mma.sync.aligned.m16n8k8.row.col.f32.tf32.tf32.f32 "                   \
        "{%0,%1,%2,%3}, {%4,%5,%6,%7}, {%8,%9}, {%0,%1,%2,%3};"                 \
        : "+f"((D)[0]), "+f"((D)[1]), "+f"((D)[2]), "+f"((D)[3])                \
        : "r"(A0), "r"(A1), "r"(A2), "r"(A3), "r"(Bb0), "r"(Bb1))

#define MMA_BF16(D, Aa, Bb0, Bb1)                                               \
    asm("mma.sync.aligned.m16n8k16.row.col.f32.bf16.bf16.f32 "                  \
        "{%0,%1,%2,%3}, {%4,%5,%6,%7}, {%8,%9}, {%0,%1,%2,%3};"                 \
        : "+f"((D)[0]), "+f"((D)[1]), "+f"((D)[2]), "+f"((D)[3])                \
        : "r"((Aa)[0]), "r"((Aa)[1]), "r"((Aa)[2]), "r"((Aa)[3]),               \
          "r"(Bb0), "r"(Bb1))

#define LDMATRIX_X4(Aa, addr)                                                   \
    asm volatile("ldmatrix.sync.aligned.m8n8.x4.shared.b16 {%0,%1,%2,%3}, [%4];"\
        : "=r"((Aa)[0]), "=r"((Aa)[1]), "=r"((Aa)[2]), "=r"((Aa)[3])            \
        : "r"(addr))

// ---------------------------------------------------------------------------
// Prep: 64-row CTAs (grid 256, occ 2). Wh = h@W via tf32 hi/lo mma (fp32
// accurate). Outputs: WhT hi/lo bf16 [b][col][k]; f1/f2 -> 4 exps per node.
// ---------------------------------------------------------------------------
__global__ void __launch_bounds__(256) prep_mma(const float* __restrict__ h,
                                                const float* __restrict__ W,
                                                const float* __restrict__ a) {
    extern __shared__ float sp_[];
    float* hs  = sp_;                        // [64][132]
    float* WsH = hs + 64*HSTR;               // [128][72]
    float* WsL = WsH + FIN*WSTR;             // [128][72]
    float* as_ = WsL + FIN*WSTR;             // [128]
    float* f1p = as_ + 128;                  // [2][64]
    float* f2p = f1p + 128;                  // [2][64]

    const int tid = threadIdx.x;
    const int i0 = blockIdx.x * 64;

    if (tid < 128) as_[tid] = a[tid];

    // W hi/lo tf32 split
#pragma unroll
    for (int it = 0; it < 8; it++) {
        const int lin = it*256 + tid;
        const int k = lin >> 4, c4 = (lin & 15) * 4;
        const float4 w = *(const float4*)(W + k*FOUT + c4);
        const float hx = cvt_tf32(w.x), hy = cvt_tf32(w.y);
        const float hz = cvt_tf32(w.z), hw = cvt_tf32(w.w);
        *(float4*)(WsH + k*WSTR + c4) = make_float4(hx, hy, hz, hw);
        *(float4*)(WsL + k*WSTR + c4) = make_float4(cvt_tf32(w.x-hx), cvt_tf32(w.y-hy),
                                                    cvt_tf32(w.z-hz), cvt_tf32(w.w-hw));
    }
    // h tile [64][128]
#pragma unroll
    for (int it = 0; it < 8; it++) {
        const int lin = it*256 + tid;
        const int r = lin >> 5, c = (lin & 31) * 4;
        *(float4*)(hs + r*HSTR + c) = *(const float4*)(h + (size_t)(i0 + r)*FIN + c);
    }
    __syncthreads();

    const int wid = tid >> 5, lane = tid & 31;
    const int gid = lane >> 2, tig = lane & 3;
    const int mt4 = wid & 3;                 // m16 tile (rows mt4*16)
    const int nh = wid >> 2;                 // n-half

    float acc[4][4] = {};
    const float* Ap = hs + (mt4*16 + gid)*HSTR + tig;
    const float* BH = WsH + tig*WSTR + nh*32 + gid;
    const float* BL = WsL + tig*WSTR + nh*32 + gid;

#pragma unroll
    for (int kq = 0; kq < 16; kq++) {
        const float x0 = Ap[kq*8],     x1 = Ap[kq*8 + 8*HSTR];
        const float x2 = Ap[kq*8 + 4], x3 = Ap[kq*8 + 4 + 8*HSTR];
        const float h0 = cvt_tf32(x0), h1 = cvt_tf32(x1);
        const float h2 = cvt_tf32(x2), h3 = cvt_tf32(x3);
        const uint32_t AH0 = __float_as_uint(h0), AH1 = __float_as_uint(h1);
        const uint32_t AH2 = __float_as_uint(h2), AH3 = __float_as_uint(h3);
        const uint32_t AL0 = __float_as_uint(cvt_tf32(x0-h0));
        const uint32_t AL1 = __float_as_uint(cvt_tf32(x1-h1));
        const uint32_t AL2 = __float_as_uint(cvt_tf32(x2-h2));
        const uint32_t AL3 = __float_as_uint(cvt_tf32(x3-h3));
        const float* bh = BH + kq*8*WSTR;
        const float* bl = BL + kq*8*WSTR;
#pragma unroll
        for (int nt = 0; nt < 4; nt++) {
            const uint32_t bh0 = __float_as_uint(bh[nt*8]);
            const uint32_t bh1 = __float_as_uint(bh[nt*8 + 4*WSTR]);
            const uint32_t bl0 = __float_as_uint(bl[nt*8]);
            const uint32_t bl1 = __float_as_uint(bl[nt*8 + 4*WSTR]);
            MMA_TF32(acc[nt], AH0, AH1, AH2, AH3, bh0, bh1);
            MMA_TF32(acc[nt], AH0, AH1, AH2, AH3, bl0, bl1);
            MMA_TF32(acc[nt], AL0, AL1, AL2, AL3, bh0, bh1);
        }
    }

    // epilogue: partial f1/f2 (this warp's 32 cols), WhT hi/lo bf16 stores
    const int r0 = i0 + mt4*16 + gid, r1 = r0 + 8;
    const int bb = r0 >> 11;
    const int k0 = r0 & (N_-1), k1 = r1 & (N_-1);
    const size_t tb = (size_t)bb * FOUT * N_;

    float f1a = 0.f, f2a = 0.f, f1b = 0.f, f2b = 0.f;
#pragma unroll
    for (int nt = 0; nt < 4; nt++) {
        const int c = nh*32 + nt*8 + tig*2;
        const float a10 = as_[c], a11 = as_[c+1];
        const float a20 = as_[64+c], a21 = as_[64+c+1];
        f1a += acc[nt][0]*a10 + acc[nt][1]*a11;
        f2a += acc[nt][0]*a20 + acc[nt][1]*a21;
        f1b += acc[nt][2]*a10 + acc[nt][3]*a11;
        f2b += acc[nt][2]*a20 + acc[nt][3]*a21;
#pragma unroll
        for (int e = 0; e < 4; e++) {
            const float v = acc[nt][e];
            const __nv_bfloat16 hi = __float2bfloat16(v);
            const __nv_bfloat16 lo = __float2bfloat16(v - __bfloat162float(hi));
            const int col = c + (e & 1);
            const int kk = (e < 2) ? k0 : k1;
            g_WhTh[tb + (size_t)col*N_ + kk] = hi;
            g_WhTl[tb + (size_t)col*N_ + kk] = lo;
        }
    }
#pragma unroll
    for (int o = 1; o <= 2; o <<= 1) {
        f1a += __shfl_xor_sync(0xffffffffu, f1a, o);
        f2a += __shfl_xor_sync(0xffffffffu, f2a, o);
        f1b += __shfl_xor_sync(0xffffffffu, f1b, o);
        f2b += __shfl_xor_sync(0xffffffffu, f2b, o);
    }
    if (tig == 0) {
        const int ri = mt4*16 + gid;
        f1p[nh*64 + ri] = f1a;   f1p[nh*64 + ri + 8] = f1b;
        f2p[nh*64 + ri] = f2a;   f2p[nh*64 + ri + 8] = f2b;
    }
    __syncthreads();
    if (tid < 64) {
        const float f1 = f1p[tid] + f1p[64 + tid];
        const float f2 = f2p[tid] + f2p[64 + tid];
        const int node = i0 + tid;
        g_E1p[node] = expf(f1);     g_E1n[node] = expf(0.2f*f1);
        g_E2p[node] = expf(f2);     g_E2n[node] = expf(0.2f*f2);
    }
}

// ---------------------------------------------------------------------------
// Main: CTA = (128 rows, batch, 1024-j chunk); 16 stages of BK=64.
// P bf16 built to smem (fragment-friendly 144B stride), A via ldmatrix.x4,
// B = WhT hi/lo bf16 via cp.async (n-major; each B-frag reg = 1 LDS.32),
// ones-row -> Z from the same bf16 P (cancellation). bf16 m16n8k16 mma.
// ---------------------------------------------------------------------------
__global__ void __launch_bounds__(256,2) gat_mma(const int* __restrict__ adj) {
    extern __shared__ __nv_bfloat16 smb[];
    const uint32_t sb = smem_u32(smb);
    const int tid = threadIdx.x;
    const int b  = blockIdx.y;
    const int sp = blockIdx.z;
    const int i0 = blockIdx.x * BM;
    const int js = sp * JCH;
    const int nodeBase = b * N_;

    const int rg = tid >> 4;          // P rows rg*8..+7
    const int cg = tid & 15;          // P cols cg*4..+3 (within BK)
    const int wid = tid >> 5, lane = tid & 31;
    const int gid = lane >> 2, tig = lane & 3;
    const int am = (wid & 3) * 32;    // warp m-offset (2 m16 tiles)
    const int nw = wid >> 2;          // warp n-half

    // row scalars
    float e1p[8], e1n[8];
#pragma unroll
    for (int r = 0; r < 8; r++) {
        const int node = nodeBase + i0 + rg*8 + r;
        e1p[r] = g_E1p[node];
        e1n[r] = g_E1n[node];
    }

    // ones/zeros rows 128..135 of both B buffers
    for (int idx = tid; idx < 2*8*PSTRB; idx += 256) {
        const int buf = idx / (8*PSTRB);
        const int rem = idx - buf*(8*PSTRB);
        const int rr = rem / PSTRB, cc = rem - rr*PSTRB;
        smb[(buf ? OFF_B1 : OFF_B0) + (128 + rr)*PSTRB + cc] =
            (rr == 0 && cc < 64) ? __float2bfloat16(1.0f) : __float2bfloat16(0.0f);
    }

    // B staging: thread t covers row t>>1, 64B half (t&1)
    const int brow = tid >> 1, bhalf = (tid & 1) * 32;
    const __nv_bfloat16* bsrc0 = (brow < 64)
        ? (g_WhTh + (size_t)b*FOUT*N_ + (size_t)brow*N_ + js + bhalf)
        : (g_WhTl + (size_t)b*FOUT*N_ + (size_t)(brow-64)*N_ + js + bhalf);

#define CPB(S) do {                                                              \
        const __nv_bfloat16* _s = bsrc0 + (S)*BK;                                \
        const uint32_t _d = sb + ((((S)&1) ? OFF_B1 : OFF_B0)                    \
                                  + brow*PSTRB + bhalf)*2;                       \
        _Pragma("unroll")                                                        \
        for (int q = 0; q < 4; q++)                                              \
            cp16(_d + q*16, _s + q*8);                                           \
        CP_COMMIT();                                                             \
    } while (0)

    const int* adjB = adj + (size_t)b*N_*N_ + (size_t)(i0 + rg*8)*N_ + js + cg*4;
    int4 a4[8]; float4 p2v, n2v;

#define PF(S) do {                                                               \
        _Pragma("unroll")                                                        \
        for (int r = 0; r < 8; r++)                                              \
            a4[r] = __ldcs((const int4*)(adjB + (size_t)r*N_ + (S)*BK));         \
        const int _cn = nodeBase + js + (S)*BK + cg*4;                           \
        p2v = *(const float4*)(g_E2p + _cn);                                     \
        n2v = *(const float4*)(g_E2n + _cn);                                     \
    } while (0)

    CPB(0);
    PF(0);

    // ldmatrix per-thread byte offsets for the 2 m-tiles
    uint32_t aoff[2];
#pragma unroll
    for (int mt = 0; mt < 2; mt++)
        aoff[mt] = ((am + mt*16 + (lane & 7) + ((lane >> 3) & 1)*8)*PSTRB
                    + (lane >> 4)*8) * 2;

    float acc[2][4][4] = {};
    float accZ[2][4] = {};

    for (int s = 0; s < NST; s++) {
        const uint32_t pOff = (s & 1) ? OFF_P1 : OFF_P0;
        const float p2a[4] = {p2v.x, p2v.y, p2v.z, p2v.w};
        const float n2a[4] = {n2v.x, n2v.y, n2v.z, n2v.w};

        // ---- P build (bf16) + STS.64 ----
#pragma unroll
        for (int r = 0; r < 8; r++) {
            const int am4[4] = {a4[r].x, a4[r].y, a4[r].z, a4[r].w};
            float pv[4];
#pragma unroll
            for (int c = 0; c < 4; c++) {
                const float v = fmaxf(e1p[r]*p2a[c], e1n[r]*n2a[c]);
                pv[c] = (am4[c] != 0) ? v : 0.f;
            }
            *(uint2*)(smb + pOff + (rg*8 + r)*PSTRB + cg*4) =
                make_uint2(pack_bf16x2(pv[0], pv[1]), pack_bf16x2(pv[2], pv[3]));
        }

        if (s + 1 < NST) PF(s + 1);     // issue adj LDG early

        CP_WAIT0();                     // B(s) landed
        __syncthreads();                // P(s)+B(s) visible; prev GEMM done
        if (s + 1 < NST) CPB(s + 1);

        // ---- GEMM: 4 kq x (2 mt ldmatrix; 4 nt x hi+lo; ones) ----
        const uint32_t pB = sb + pOff*2;
        const __nv_bfloat16* Bs = smb + ((s & 1) ? OFF_B1 : OFF_B0);
#pragma unroll
        for (int kq = 0; kq < 4; kq++) {
            uint32_t A[2][4];
            LDMATRIX_X4(A[0], pB + aoff[0] + kq*32);
            LDMATRIX_X4(A[1], pB + aoff[1] + kq*32);
            const __nv_bfloat16* Bk = Bs + kq*16 + tig*2;
#pragma unroll
            for (int nt = 0; nt < 4; nt++) {
                const int nrow = nw*32 + nt*8 + gid;
                const uint32_t bh0 = *(const uint32_t*)(Bk + nrow*PSTRB);
                const uint32_t bh1 = *(const uint32_t*)(Bk + nrow*PSTRB + 8);
                const uint32_t bl0 = *(const uint32_t*)(Bk + (nrow+64)*PSTRB);
                const uint32_t bl1 = *(const uint32_t*)(Bk + (nrow+64)*PSTRB + 8);
                MMA_BF16(acc[0][nt], A[0], bh0, bh1);
                MMA_BF16(acc[1][nt], A[1], bh0, bh1);
                MMA_BF16(acc[0][nt], A[0], bl0, bl1);
                MMA_BF16(acc[1][nt], A[1], bl0, bl1);
            }
            if (nw == 1) {
                const uint32_t bo0 = *(const uint32_t*)(Bk + (128+gid)*PSTRB);
                const uint32_t bo1 = *(const uint32_t*)(Bk + (128+gid)*PSTRB + 8);
                MMA_BF16(accZ[0], A[0], bo0, bo1);
                MMA_BF16(accZ[1], A[1], bo0, bo1);
            }
        }
    }

    // ---- store partials ----
    const size_t obase = ((size_t)sp*NNODE + nodeBase + i0) * FOUT;
#pragma unroll
    for (int mt = 0; mt < 2; mt++) {
        const int row = am + mt*16 + gid;
#pragma unroll
        for (int nt = 0; nt < 4; nt++) {
            const int col = nw*32 + nt*8 + tig*2;
            *(float2*)&g_acc[obase + (size_t)row*FOUT + col] =
                make_float2(acc[mt][nt][0], acc[mt][nt][1]);
            *(float2*)&g_acc[obase + (size_t)(row + 8)*FOUT + col] =
                make_float2(acc[mt][nt][2], acc[mt][nt][3]);
        }
        if (nw == 1 && tig == 0) {
            g_Z[(size_t)sp*NNODE + nodeBase + i0 + row]     = accZ[mt][0];
            g_Z[(size_t)sp*NNODE + nodeBase + i0 + row + 8] = accZ[mt][2];
        }
    }
}

// ---------------------------------------------------------------------------
__global__ void __launch_bounds__(256) combine_kernel(float* __restrict__ out) {
    const int idx = blockIdx.x * 256 + threadIdx.x;
    const int node = idx >> 4;
    const int f4 = (idx & 15) * 4;
    float sx = 0.f, sy = 0.f, sz = 0.f, sw = 0.f, z = 0.f;
#pragma unroll
    for (int sp = 0; sp < SPLIT; sp++) {
        const float4 v = *(const float4*)&g_acc[((size_t)sp*NNODE + node)*FOUT + f4];
        sx += v.x; sy += v.y; sz += v.z; sw += v.w;
        z += g_Z[(size_t)sp*NNODE + node];
    }
    const float inv = 1.0f / z;
    *(float4*)&out[(size_t)node*FOUT + f4] = make_float4(sx*inv, sy*inv, sz*inv, sw*inv);
}

// ---------------------------------------------------------------------------
extern "C" void kernel_launch(void* const* d_in, const int* in_sizes, int n_in,
                              void* d_out, int out_size) {
    const float* h   = (const float*)d_in[0];
    const float* W   = (const float*)d_in[1];
    const float* a   = (const float*)d_in[2];
    const int*   adj = (const int*)d_in[3];
    float* out = (float*)d_out;

    cudaFuncSetAttribute(prep_mma, cudaFuncAttributeMaxDynamicSharedMemorySize, PREP_SMEM);
    prep_mma<<<NNODE/64, 256, PREP_SMEM>>>(h, W, a);

    cudaFuncSetAttribute(gat_mma, cudaFuncAttributeMaxDynamicSharedMemorySize, GAT_SMEM);
    dim3 grid(N_/BM, B_, SPLIT);
    gat_mma<<<grid, 256, GAT_SMEM>>>(adj);

    combine_kernel<<<(NNODE*16)/256, 256>>>(out);
}

// round 7
// speedup vs baseline: 3.6543x; 1.1377x over previous
#include <cuda_runtime.h>
#include <cuda_fp16.h>
#include <math.h>
#include <stdint.h>

#define B_ 8
#define N_ 2048
#define FIN 128
#define FOUT 64
#define NNODE (B_*N_)

#define SPLIT 2
#define JCH (N_/SPLIT)      // 1024
#define BK 64
#define NST (JCH/BK)        // 16
#define BM 128

// ---- gat smem (fp16 units) ----
#define PSTRB 72                      // 144B row stride (conflict-free ldmatrix/LDS)
#define PBUFB (BM*PSTRB)              // 9216
#define BROWS 72                      // 64 Wh cols + 8 ones/zeros rows
#define BBUFB (BROWS*PSTRB)           // 5184
#define OFF_P0 0
#define OFF_P1 PBUFB
#define OFF_B0 (2*PBUFB)
#define OFF_B1 (2*PBUFB + BBUFB)
#define GAT_SMEM ((2*PBUFB + 2*BBUFB)*2)   // 57600 B

// ---- prep smem (float units) ----
#define HSTR 132
#define WSTR 72
#define PREP_SMEM ((64*HSTR + 2*FIN*WSTR + 128 + 256)*4)   // 109056 B

// ---------------- scratch ----------------------------------------------------
__device__ __half g_WhT[(size_t)B_*FOUT*N_];    // [b][col][k] fp16
__device__ float g_f1[NNODE], g_f2[NNODE];
__device__ float g_E1p[NNODE], g_E1n[NNODE];    // row-rescaled
__device__ float g_E2p[NNODE], g_E2n[NNODE];
__device__ float g_acc[(size_t)SPLIT*NNODE*FOUT];
__device__ float g_Z[(size_t)SPLIT*NNODE];

// ---------------- helpers ----------------------------------------------------
__device__ __forceinline__ uint32_t smem_u32(const void* p) {
    uint32_t a;
    asm("{ .reg .u64 t; cvta.to.shared.u64 t, %1; cvt.u32.u64 %0, t; }" : "=r"(a) : "l"(p));
    return a;
}
__device__ __forceinline__ float cvt_tf32(float x) {
    uint32_t u;
    asm("cvt.rna.tf32.f32 %0, %1;" : "=r"(u) : "f"(x));
    return __uint_as_float(u);
}
__device__ __forceinline__ void cp16(uint32_t dst, const void* src) {
    asm volatile("cp.async.cg.shared.global [%0], [%1], 16;" :: "r"(dst), "l"(src));
}
#define CP_COMMIT() asm volatile("cp.async.commit_group;" ::: "memory")
#define CP_WAIT0()  asm volatile("cp.async.wait_group 0;" ::: "memory")

#define MMA_TF32(D, A0, A1, A2, A3, Bb0, Bb1)                                   \
    asm("mma.sync.aligned.m16n8k8.row.col.f32.tf32.tf32.f32 "                   \
        "{%0,%1,%2,%3}, {%4,%5,%6,%7}, {%8,%9}, {%0,%1,%2,%3};"                 \
        : "+f"((D)[0]), "+f"((D)[1]), "+f"((D)[2]), "+f"((D)[3])                \
        : "r"(A0), "r"(A1), "r"(A2), "r"(A3), "r"(Bb0), "r"(Bb1))

#define MMA_F16(D, Aa, Bb0, Bb1)                                                \
    asm("mma.sync.aligned.m16n8k16.row.col.f32.f16.f16.f32 "                    \
        "{%0,%1,%2,%3}, {%4,%5,%6,%7}, {%8,%9}, {%0,%1,%2,%3};"                 \
        : "+f"((D)[0]), "+f"((D)[1]), "+f"((D)[2]), "+f"((D)[3])                \
        : "r"((Aa)[0]), "r"((Aa)[1]), "r"((Aa)[2]), "r"((Aa)[3]),               \
          "r"(Bb0), "r"(Bb1))

#define LDMATRIX_X4(Aa, addr)                                                   \
    asm volatile("ldmatrix.sync.aligned.m8n8.x4.shared.b16 {%0,%1,%2,%3}, [%4];"\
        : "=r"((Aa)[0]), "=r"((Aa)[1]), "=r"((Aa)[2]), "=r"((Aa)[3])            \
        : "r"(addr))

// ---------------------------------------------------------------------------
// Prep: 64-row CTAs. Wh = h@W via tf32 mma (A=h single tf32, B=W hi/lo split).
// Outputs: WhT fp16 [b][col][k] via smem transpose + coalesced STG; raw f1/f2.
// ---------------------------------------------------------------------------
__global__ void __launch_bounds__(256) prep_mma(const float* __restrict__ h,
                                                const float* __restrict__ W,
                                                const float* __restrict__ a) {
    extern __shared__ float sp_[];
    float* hs  = sp_;                        // [64][132]
    float* WsH = hs + 64*HSTR;               // [128][72]
    float* WsL = WsH + FIN*WSTR;             // [128][72]
    float* as_ = WsL + FIN*WSTR;             // [128]
    float* f1p = as_ + 128;                  // [2][64]
    float* f2p = f1p + 128;                  // [2][64]

    const int tid = threadIdx.x;
    const int i0 = blockIdx.x * 64;

    if (tid < 128) as_[tid] = a[tid];

    // W hi/lo tf32 split
#pragma unroll
    for (int it = 0; it < 8; it++) {
        const int lin = it*256 + tid;
        const int k = lin >> 4, c4 = (lin & 15) * 4;
        const float4 w = *(const float4*)(W + k*FOUT + c4);
        const float hx = cvt_tf32(w.x), hy = cvt_tf32(w.y);
        const float hz = cvt_tf32(w.z), hw = cvt_tf32(w.w);
        *(float4*)(WsH + k*WSTR + c4) = make_float4(hx, hy, hz, hw);
        *(float4*)(WsL + k*WSTR + c4) = make_float4(cvt_tf32(w.x-hx), cvt_tf32(w.y-hy),
                                                    cvt_tf32(w.z-hz), cvt_tf32(w.w-hw));
    }
    // h tile [64][128]
#pragma unroll
    for (int it = 0; it < 8; it++) {
        const int lin = it*256 + tid;
        const int r = lin >> 5, c = (lin & 31) * 4;
        *(float4*)(hs + r*HSTR + c) = *(const float4*)(h + (size_t)(i0 + r)*FIN + c);
    }
    __syncthreads();

    const int wid = tid >> 5, lane = tid & 31;
    const int gid = lane >> 2, tig = lane & 3;
    const int mt4 = wid & 3;                 // m16 tile (rows mt4*16)
    const int nh = wid >> 2;                 // n-half

    float acc[4][4] = {};
    const float* Ap = hs + (mt4*16 + gid)*HSTR + tig;
    const float* BH = WsH + tig*WSTR + nh*32 + gid;
    const float* BL = WsL + tig*WSTR + nh*32 + gid;

#pragma unroll
    for (int kq = 0; kq < 16; kq++) {
        const uint32_t A0 = __float_as_uint(cvt_tf32(Ap[kq*8]));
        const uint32_t A1 = __float_as_uint(cvt_tf32(Ap[kq*8 + 8*HSTR]));
        const uint32_t A2 = __float_as_uint(cvt_tf32(Ap[kq*8 + 4]));
        const uint32_t A3 = __float_as_uint(cvt_tf32(Ap[kq*8 + 4 + 8*HSTR]));
        const float* bh = BH + kq*8*WSTR;
        const float* bl = BL + kq*8*WSTR;
#pragma unroll
        for (int nt = 0; nt < 4; nt++) {
            const uint32_t bh0 = __float_as_uint(bh[nt*8]);
            const uint32_t bh1 = __float_as_uint(bh[nt*8 + 4*WSTR]);
            const uint32_t bl0 = __float_as_uint(bl[nt*8]);
            const uint32_t bl1 = __float_as_uint(bl[nt*8 + 4*WSTR]);
            MMA_TF32(acc[nt], A0, A1, A2, A3, bh0, bh1);
            MMA_TF32(acc[nt], A0, A1, A2, A3, bl0, bl1);
        }
    }

    // f1/f2 partials (fp32 accumulators, before fp16 rounding)
    float f1a = 0.f, f2a = 0.f, f1b = 0.f, f2b = 0.f;
#pragma unroll
    for (int nt = 0; nt < 4; nt++) {
        const int c = nh*32 + nt*8 + tig*2;
        const float a10 = as_[c], a11 = as_[c+1];
        const float a20 = as_[64+c], a21 = as_[64+c+1];
        f1a += acc[nt][0]*a10 + acc[nt][1]*a11;
        f2a += acc[nt][0]*a20 + acc[nt][1]*a21;
        f1b += acc[nt][2]*a10 + acc[nt][3]*a11;
        f2b += acc[nt][2]*a20 + acc[nt][3]*a21;
    }
#pragma unroll
    for (int o = 1; o <= 2; o <<= 1) {
        f1a += __shfl_xor_sync(0xffffffffu, f1a, o);
        f2a += __shfl_xor_sync(0xffffffffu, f2a, o);
        f1b += __shfl_xor_sync(0xffffffffu, f1b, o);
        f2b += __shfl_xor_sync(0xffffffffu, f2b, o);
    }
    if (tig == 0) {
        const int ri = mt4*16 + gid;
        f1p[nh*64 + ri] = f1a;   f1p[nh*64 + ri + 8] = f1b;
        f2p[nh*64 + ri] = f2a;   f2p[nh*64 + ri + 8] = f2b;
    }
    __syncthreads();                 // GEMM reads of hs done; f1p/f2p visible

    // WhT transpose tile in smem (aliases hs region): Wt[col][k] fp16, stride 72
    __half* Wt = (__half*)sp_;
#pragma unroll
    for (int nt = 0; nt < 4; nt++) {
#pragma unroll
        for (int e = 0; e < 4; e++) {
            const int col = nh*32 + nt*8 + tig*2 + (e & 1);
            const int kl = mt4*16 + gid + ((e >> 1) << 3);
            Wt[col*72 + kl] = __float2half(acc[nt][e]);
        }
    }
    __syncthreads();

    // coalesced STG of WhT + f1/f2
    const int bb = i0 >> 11;
    const int kbase = i0 & (N_-1);
    {
        const int col = tid >> 2, seg = tid & 3;
        const __half* srcw = Wt + col*72 + seg*16;
        __half* dstw = g_WhT + (size_t)bb*FOUT*N_ + (size_t)col*N_ + kbase + seg*16;
        *(uint4*)dstw = *(const uint4*)srcw;
        *(uint4*)(dstw + 8) = *(const uint4*)(srcw + 8);
    }
    if (tid < 64) {
        g_f1[i0 + tid] = f1p[tid] + f1p[64 + tid];
        g_f2[i0 + tid] = f2p[tid] + f2p[64 + tid];
    }
}

// ---------------------------------------------------------------------------
// Scalars: per batch, M2 = max_j f2; m_i = leakyrelu(f1_i + M2);
// E1p = exp(f1-m), E1n = exp(0.2 f1 - m), E2p = exp(f2), E2n = exp(0.2 f2).
// Row rescale makes all P values <= 1 (fp16-safe); cancels in softmax.
// ---------------------------------------------------------------------------
__global__ void __launch_bounds__(256) scalars_kernel() {
    __shared__ float red[8];
    __shared__ float M2s;
    const int b = blockIdx.x, tid = threadIdx.x;
    const int base = b * N_;

    float m = -1e30f;
#pragma unroll
    for (int k = 0; k < 8; k++) m = fmaxf(m, g_f2[base + tid + k*256]);
#pragma unroll
    for (int o = 16; o > 0; o >>= 1) m = fmaxf(m, __shfl_xor_sync(0xffffffffu, m, o));
    if ((tid & 31) == 0) red[tid >> 5] = m;
    __syncthreads();
    if (tid == 0) {
        float mm = red[0];
#pragma unroll
        for (int i = 1; i < 8; i++) mm = fmaxf(mm, red[i]);
        M2s = mm;
    }
    __syncthreads();
    const float M2 = M2s;

#pragma unroll
    for (int k = 0; k < 8; k++) {
        const int node = base + tid + k*256;
        const float f1 = g_f1[node], f2 = g_f2[node];
        const float S = f1 + M2;
        const float mi = (S >= 0.f) ? S : 0.2f*S;
        g_E1p[node] = expf(f1 - mi);
        g_E1n[node] = expf(0.2f*f1 - mi);
        g_E2p[node] = expf(f2);
        g_E2n[node] = expf(0.2f*f2);
    }
}

// ---------------------------------------------------------------------------
// Main: CTA = (128 rows, batch, 1024-j chunk); 16 stages of BK=64.
// P fp16 (row-rescaled, <=1) built to smem; A via ldmatrix.x4; B = WhT fp16
// (single) via cp.async; ones row -> Z on tensor core. fp16 m16n8k16 mma.
// ---------------------------------------------------------------------------
__global__ void __launch_bounds__(256,2) gat_mma(const int* __restrict__ adj) {
    extern __shared__ __half smb[];
    const uint32_t sb = smem_u32(smb);
    const int tid = threadIdx.x;
    const int b  = blockIdx.y;
    const int sp = blockIdx.z;
    const int i0 = blockIdx.x * BM;
    const int js = sp * JCH;
    const int nodeBase = b * N_;

    const int rg = tid >> 4;          // P rows rg*8..+7
    const int cg = tid & 15;          // P cols cg*4..+3 (within BK)
    const int wid = tid >> 5, lane = tid & 31;
    const int gid = lane >> 2, tig = lane & 3;
    const int am = (wid & 3) * 32;    // warp m-offset (2 m16 tiles)
    const int nw = wid >> 2;          // warp n-half

    float e1p[8], e1n[8];
#pragma unroll
    for (int r = 0; r < 8; r++) {
        const int node = nodeBase + i0 + rg*8 + r;
        e1p[r] = g_E1p[node];
        e1n[r] = g_E1n[node];
    }

    // ones/zeros rows 64..71 of both B buffers
    for (int idx = tid; idx < 2*8*PSTRB; idx += 256) {
        const int buf = idx / (8*PSTRB);
        const int rem = idx - buf*(8*PSTRB);
        const int rr = rem / PSTRB, cc = rem - rr*PSTRB;
        smb[(buf ? OFF_B1 : OFF_B0) + (64 + rr)*PSTRB + cc] =
            (rr == 0 && cc < 64) ? __float2half(1.0f) : __float2half(0.0f);
    }

    // B staging: 64 rows x 128B; thread covers (row tid>>3, seg tid&7), 2 passes
    const int brow = tid >> 3, bseg = (tid & 7) * 8;
    const __half* bsrc = g_WhT + (size_t)b*FOUT*N_ + (size_t)brow*N_ + js + bseg;

#define CPB(S) do {                                                              \
        const uint32_t _bo = ((S)&1) ? OFF_B1 : OFF_B0;                          \
        cp16(sb + (_bo + brow*PSTRB + bseg)*2,        bsrc + (S)*BK);            \
        cp16(sb + (_bo + (brow+32)*PSTRB + bseg)*2,   bsrc + (size_t)32*N_ + (S)*BK); \
        CP_COMMIT();                                                             \
    } while (0)

    const int* adjB = adj + (size_t)b*N_*N_ + (size_t)(i0 + rg*8)*N_ + js + cg*4;
    int4 a4[8]; float4 p2v, n2v;

#define PF(S) do {                                                               \
        _Pragma("unroll")                                                        \
        for (int r = 0; r < 8; r++)                                              \
            a4[r] = __ldcs((const int4*)(adjB + (size_t)r*N_ + (S)*BK));         \
        const int _cn = nodeBase + js + (S)*BK + cg*4;                           \
        p2v = *(const float4*)(g_E2p + _cn);                                     \
        n2v = *(const float4*)(g_E2n + _cn);                                     \
    } while (0)

    CPB(0);
    PF(0);

    // ldmatrix per-thread byte offsets for the 2 m-tiles
    uint32_t aoff[2];
#pragma unroll
    for (int mt = 0; mt < 2; mt++)
        aoff[mt] = ((am + mt*16 + (lane & 7) + ((lane >> 3) & 1)*8)*PSTRB
                    + (lane >> 4)*8) * 2;

    float acc[2][4][4] = {};
    float accZ[2][4] = {};

    for (int s = 0; s < NST; s++) {
        const uint32_t pOff = (s & 1) ? OFF_P1 : OFF_P0;
        const float p2a[4] = {p2v.x, p2v.y, p2v.z, p2v.w};
        const float n2a[4] = {n2v.x, n2v.y, n2v.z, n2v.w};

        // ---- P build (fp16, values <= 1) + STS.64 ----
#pragma unroll
        for (int r = 0; r < 8; r++) {
            const int am4[4] = {a4[r].x, a4[r].y, a4[r].z, a4[r].w};
            float pv[4];
#pragma unroll
            for (int c = 0; c < 4; c++) {
                const float v = fmaxf(e1p[r]*p2a[c], e1n[r]*n2a[c]);
                pv[c] = (am4[c] != 0) ? v : 0.f;
            }
            __half2 h01 = __floats2half2_rn(pv[0], pv[1]);
            __half2 h23 = __floats2half2_rn(pv[2], pv[3]);
            uint2 pk;
            pk.x = *reinterpret_cast<uint32_t*>(&h01);
            pk.y = *reinterpret_cast<uint32_t*>(&h23);
            *(uint2*)(smb + pOff + (rg*8 + r)*PSTRB + cg*4) = pk;
        }

        if (s + 1 < NST) PF(s + 1);     // issue adj LDG early

        CP_WAIT0();                     // B(s) landed
        __syncthreads();                // P(s)+B(s) visible; prev GEMM done
        if (s + 1 < NST) CPB(s + 1);

        // ---- GEMM: 4 kq x (2 ldmatrix + 4 nt + ones) ----
        const uint32_t pB = sb + pOff*2;
        const __half* Bs = smb + ((s & 1) ? OFF_B1 : OFF_B0);
#pragma unroll
        for (int kq = 0; kq < 4; kq++) {
            uint32_t A[2][4];
            LDMATRIX_X4(A[0], pB + aoff[0] + kq*32);
            LDMATRIX_X4(A[1], pB + aoff[1] + kq*32);
            const __half* Bk = Bs + kq*16 + tig*2;
#pragma unroll
            for (int nt = 0; nt < 4; nt++) {
                const int nrow = nw*32 + nt*8 + gid;
                const uint32_t b0 = *(const uint32_t*)(Bk + nrow*PSTRB);
                const uint32_t b1 = *(const uint32_t*)(Bk + nrow*PSTRB + 8);
                MMA_F16(acc[0][nt], A[0], b0, b1);
                MMA_F16(acc[1][nt], A[1], b0, b1);
            }
            if (nw == 1) {
                const uint32_t bo0 = *(const uint32_t*)(Bk + (64+gid)*PSTRB);
                const uint32_t bo1 = *(const uint32_t*)(Bk + (64+gid)*PSTRB + 8);
                MMA_F16(accZ[0], A[0], bo0, bo1);
                MMA_F16(accZ[1], A[1], bo0, bo1);
            }
        }
    }

    // ---- store partials ----
    const size_t obase = ((size_t)sp*NNODE + nodeBase + i0) * FOUT;
#pragma unroll
    for (int mt = 0; mt < 2; mt++) {
        const int row = am + mt*16 + gid;
#pragma unroll
        for (int nt = 0; nt < 4; nt++) {
            const int col = nw*32 + nt*8 + tig*2;
            *(float2*)&g_acc[obase + (size_t)row*FOUT + col] =
                make_float2(acc[mt][nt][0], acc[mt][nt][1]);
            *(float2*)&g_acc[obase + (size_t)(row + 8)*FOUT + col] =
                make_float2(acc[mt][nt][2], acc[mt][nt][3]);
        }
        if (nw == 1 && tig == 0) {
            g_Z[(size_t)sp*NNODE + nodeBase + i0 + row]     = accZ[mt][0];
            g_Z[(size_t)sp*NNODE + nodeBase + i0 + row + 8] = accZ[mt][2];
        }
    }
}

// ---------------------------------------------------------------------------
__global__ void __launch_bounds__(256) combine_kernel(float* __restrict__ out) {
    const int idx = blockIdx.x * 256 + threadIdx.x;
    const int node = idx >> 4;
    const int f4 = (idx & 15) * 4;
    float sx = 0.f, sy = 0.f, sz = 0.f, sw = 0.f, z = 0.f;
#pragma unroll
    for (int sp = 0; sp < SPLIT; sp++) {
        const float4 v = *(const float4*)&g_acc[((size_t)sp*NNODE + node)*FOUT + f4];
        sx += v.x; sy += v.y; sz += v.z; sw += v.w;
        z += g_Z[(size_t)sp*NNODE + node];
    }
    const float inv = 1.0f / z;
    *(float4*)&out[(size_t)node*FOUT + f4] = make_float4(sx*inv, sy*inv, sz*inv, sw*inv);
}

// ---------------------------------------------------------------------------
extern "C" void kernel_launch(void* const* d_in, const int* in_sizes, int n_in,
                              void* d_out, int out_size) {
    const float* h   = (const float*)d_in[0];
    const float* W   = (const float*)d_in[1];
    const float* a   = (const float*)d_in[2];
    const int*   adj = (const int*)d_in[3];
    float* out = (float*)d_out;

    cudaFuncSetAttribute(prep_mma, cudaFuncAttributeMaxDynamicSharedMemorySize, PREP_SMEM);
    prep_mma<<<NNODE/64, 256, PREP_SMEM>>>(h, W, a);

    scalars_kernel<<<B_, 256>>>();

    cudaFuncSetAttribute(gat_mma, cudaFuncAttributeMaxDynamicSharedMemorySize, GAT_SMEM);
    dim3 grid(N_/BM, B_, SPLIT);
    gat_mma<<<grid, 256, GAT_SMEM>>>(adj);

    combine_kernel<<<(NNODE*16)/256, 256>>>(out);
}